// round 15
// baseline (speedup 1.0000x reference)
#include <cuda_runtime.h>
#include <cuda_fp16.h>
#include <cooperative_groups.h>
#include <cstdint>
#include <cstddef>

namespace cg = cooperative_groups;

#define N_NODES 50000
#define N_PAD   50048
#define N_EDGES 800000
#define C_HID   256
#define C_OUT   128
#define NCHUNK  ((N_NODES + 255) / 256)    // 196 scan chunks of 256 nodes
#define N_MASKB (N_NODES * C_HID / 8)      // 1,600,000 mask bytes
#define MB_P1   800000                     // phase-1 mask bytes [0, 800K)
#define NCVT    (N_NODES * (C_OUT / 4))    // 1,600,000 float4s of x

// ---------------- scratch (static device globals; no allocation) ----------------
// g_dega & g_cnt are accumulators: zero at process start (BSS), re-zeroed by the
// FINAL kernel (k_aggh CLEAN) so each graph replay starts clean.
__device__ __align__(16) float    g_dega[N_NODES];     // deg = 1 + g_dega
__device__ __align__(16) float    g_dinv[N_NODES];
__device__ __align__(16) int      g_src [N_EDGES];
__device__ __align__(16) int      g_dst [N_EDGES];
__device__ __align__(16) int      g_cnt [N_NODES];
__device__ __align__(16) int      g_rp  [N_NODES];     // chunk-local exclusive scan
__device__ __align__(16) int      g_cur [N_NODES];
__device__ __align__(16) int      g_bsum[NCHUNK];
__device__ __align__(16) int      g_boff[NCHUNK];      // chunk offsets (for agg2)
__device__ __align__(16) int2     g_ep  [N_EDGES];     // CSR: packed {src, norm-bits}
__device__ __align__(16) uint8_t  g_mask8[N_MASKB];    // JAX dropout keep-bits
__device__ __align__(16) __half   g_xh  [(size_t)N_NODES * C_OUT];
__device__ __align__(16) float    g_ax  [(size_t)N_PAD * C_OUT];
__device__ __align__(16) __half   g_h1h [(size_t)N_PAD * C_HID];
__device__ __align__(16) __half   g_h2h [(size_t)N_PAD * C_OUT];

// ---------------- threefry-2x32 (JAX partitionable convention) ----------------
__device__ __forceinline__ uint32_t rotl32(uint32_t x, int d) {
    return (x << d) | (x >> (32 - d));
}
__device__ __forceinline__ void threefry2x32(uint32_t k0, uint32_t k1,
                                             uint32_t& x0, uint32_t& x1) {
    uint32_t ks0 = k0, ks1 = k1, ks2 = k0 ^ k1 ^ 0x1BD11BDAu;
    x0 += ks0; x1 += ks1;
#define TF_GROUP(a,b,c,d) \
    x0 += x1; x1 = rotl32(x1,a); x1 ^= x0; \
    x0 += x1; x1 = rotl32(x1,b); x1 ^= x0; \
    x0 += x1; x1 = rotl32(x1,c); x1 ^= x0; \
    x0 += x1; x1 = rotl32(x1,d); x1 ^= x0;
    TF_GROUP(13,15,26,6)   x0 += ks1; x1 += ks2 + 1u;
    TF_GROUP(17,29,16,24)  x0 += ks2; x1 += ks0 + 2u;
    TF_GROUP(13,15,26,6)   x0 += ks0; x1 += ks1 + 3u;
    TF_GROUP(17,29,16,24)  x0 += ks1; x1 += ks2 + 4u;
    TF_GROUP(13,15,26,6)   x0 += ks2; x1 += ks0 + 5u;
#undef TF_GROUP
}
__device__ __forceinline__ uint32_t drop_keep_bit(uint32_t i) {
    uint32_t x0 = 0u, x1 = i;
    threefry2x32(0u, 42u, x0, x1);
    return ((x0 ^ x1) >> 31) ^ 1u;
}
__device__ __forceinline__ void mask_byte(uint32_t b) {
    uint32_t base = b * 8u;
    uint32_t m = 0;
#pragma unroll
    for (int j = 0; j < 8; j++) m |= drop_keep_bit(base + j) << j;
    g_mask8[b] = (uint8_t)m;
}

__device__ __forceinline__ uint32_t f2tf32(float f) {
    uint32_t r;
    asm("cvt.rna.tf32.f32 %0, %1;" : "=r"(r) : "f"(f));
    return r;
}

// ================= cooperative prep kernel: 4 phases, 3 grid syncs =================
// P1: dtype detect + x->fp16 + edge decode/count + mask[0,800K)
// P2: chunk-local exclusive scan of cnt (+dinv)
// P3: smem scan of chunk sums; CSR scatter + mask[800K,1.6M)
// P4: agg1 (ax = A_hat @ x), one warp per node, boff from smem
__global__ void __launch_bounds__(256) k_prep_all(const float* __restrict__ x,
                                                  const void* __restrict__ ei_raw,
                                                  const float* __restrict__ w) {
    cg::grid_group grid = cg::this_grid();
    __shared__ int ws[8];
    __shared__ int sb[256];
    __shared__ int sexcl[NCHUNK];
    __shared__ int s_odd, s_big, s_mode;

    const int t = threadIdx.x;
    const int gsz = gridDim.x * 256;
    const int gtid0 = blockIdx.x * 256 + t;
    const int lane = t & 31, wid = t >> 5;

    // ---- dtype detection (per block; first 1024 words, L1-hot) ----
    if (t == 0) { s_odd = 0; s_big = 0; }
    __syncthreads();
    {
        const unsigned* eiw = (const unsigned*)ei_raw;
        unsigned v0 = eiw[2 * t];
        unsigned v1 = eiw[2 * t + 1];
        if (v0 >= 0x30000000u || v1 >= 0x30000000u) atomicOr(&s_big, 1);
        if (v1 != 0u) atomicOr(&s_odd, 1);
    }
    __syncthreads();
    if (t == 0) s_mode = s_big ? 2 : (s_odd ? 1 : 0);
    __syncthreads();
    const int mode = s_mode;

    // ---- P1 ----
    for (int i = gtid0; i < NCVT; i += gsz) {
        float4 v = ((const float4*)x)[i];
        __half2 a = __floats2half2_rn(v.x, v.y);
        __half2 b = __floats2half2_rn(v.z, v.w);
        ((uint2*)g_xh)[i] = make_uint2(*(uint32_t*)&a, *(uint32_t*)&b);
        if (i < N_EDGES) {
            int s, d;
            if (mode == 2) {
                const float* ei = (const float*)ei_raw;
                s = (int)ei[i];
                d = (int)ei[N_EDGES + i];
            } else if (mode == 1) {
                const int* ei = (const int*)ei_raw;
                s = ei[i];
                d = ei[N_EDGES + i];
            } else {
                const long long* ei = (const long long*)ei_raw;
                s = (int)ei[i];
                d = (int)ei[N_EDGES + i];
            }
            s = min(max(s, 0), N_NODES - 1);
            d = min(max(d, 0), N_NODES - 1);
            g_src[i] = s; g_dst[i] = d;
            atomicAdd(&g_dega[d], w[i]);
            atomicAdd(&g_cnt[d], 1);
            if (i < MB_P1) mask_byte((uint32_t)i);
        }
    }
    grid.sync();

    // ---- P2: per-chunk (256 nodes) exclusive scan + dinv ----
    for (int c = blockIdx.x; c < NCHUNK; c += gridDim.x) {
        int i = c * 256 + t;
        int v = (i < N_NODES) ? g_cnt[i] : 0;
        if (i < N_NODES) g_dinv[i] = rsqrtf(1.0f + g_dega[i]);
        int xx = v;
#pragma unroll
        for (int o = 1; o < 32; o <<= 1) {
            int y = __shfl_up_sync(~0u, xx, o);
            if (lane >= o) xx += y;
        }
        if (lane == 31) ws[wid] = xx;
        __syncthreads();
        if (wid == 0 && lane < 8) {
            int s = ws[lane];
#pragma unroll
            for (int o = 1; o < 8; o <<= 1) {
                int y = __shfl_up_sync(0xFFu, s, o);
                if (lane >= o) s += y;
            }
            ws[lane] = s;
        }
        __syncthreads();
        int excl = xx - v + (wid > 0 ? ws[wid - 1] : 0);
        if (i < N_NODES) {
            g_rp[i]  = excl;
            g_cur[i] = excl;
        }
        if (t == 0) g_bsum[c] = ws[7];
        __syncthreads();   // protect ws/reuse across chunk iterations
    }
    grid.sync();

    // ---- P3 prologue: scan the 196 chunk sums in smem ----
    {
        int v = (t < NCHUNK) ? g_bsum[t] : 0;
        sb[t] = v;
        __syncthreads();
#pragma unroll
        for (int o = 1; o < 256; o <<= 1) {
            int y = (t >= o) ? sb[t - o] : 0;
            __syncthreads();
            sb[t] += y;
            __syncthreads();
        }
        if (t < NCHUNK) {
            sexcl[t] = sb[t] - v;
            if (blockIdx.x == 0) g_boff[t] = sb[t] - v;   // for agg2
        }
        __syncthreads();
    }
    // ---- P3: CSR scatter + mask[800K, 1.6M) ----
    for (int e = gtid0; e < N_EDGES; e += gsz) {
        mask_byte((uint32_t)(MB_P1 + e));
        int s = g_src[e], d = g_dst[e];
        float nm = g_dinv[s] * w[e] * g_dinv[d];
        int pos = atomicAdd(&g_cur[d], 1) + sexcl[d >> 8];
        if ((unsigned)pos < N_EDGES) {
            g_ep[pos] = make_int2(s, __float_as_int(nm));
        }
    }
    grid.sync();

    // ---- P4: agg1 — ax[n] = dinv^2 * x[n] + sum norm*x[src], warp per node ----
    const uint2* h4 = (const uint2*)g_xh;
    const int warp0 = (blockIdx.x * 256 + t) >> 5;
    const int nwarps = gsz >> 5;
    for (int n = warp0; n < N_NODES; n += nwarps) {
        float di = g_dinv[n];
        float sw = di * di;
        int beg = g_rp[n] + sexcl[n >> 8];
        int end = (n + 1 < N_NODES) ? (g_rp[n + 1] + sexcl[(n + 1) >> 8]) : N_EDGES;

        float4 acc;
        {
            uint2 hv = h4[(size_t)n * 32 + lane];
            float2 f0 = __half22float2(*(const __half2*)&hv.x);
            float2 f1 = __half22float2(*(const __half2*)&hv.y);
            acc = make_float4(sw * f0.x, sw * f0.y, sw * f1.x, sw * f1.y);
        }
        int j = beg;
        for (; j + 3 < end; j += 4) {
            int2 e0 = g_ep[j],   e1 = g_ep[j+1], e2 = g_ep[j+2], e3 = g_ep[j+3];
            uint2 t0 = h4[(size_t)e0.x * 32 + lane];
            uint2 t1 = h4[(size_t)e1.x * 32 + lane];
            uint2 t2 = h4[(size_t)e2.x * 32 + lane];
            uint2 t3 = h4[(size_t)e3.x * 32 + lane];
            float n0 = __int_as_float(e0.y), n1 = __int_as_float(e1.y);
            float n2 = __int_as_float(e2.y), n3 = __int_as_float(e3.y);
            float2 a0 = __half22float2(*(const __half2*)&t0.x);
            float2 a1 = __half22float2(*(const __half2*)&t0.y);
            float2 b0 = __half22float2(*(const __half2*)&t1.x);
            float2 b1 = __half22float2(*(const __half2*)&t1.y);
            float2 c0 = __half22float2(*(const __half2*)&t2.x);
            float2 c1 = __half22float2(*(const __half2*)&t2.y);
            float2 d0 = __half22float2(*(const __half2*)&t3.x);
            float2 d1 = __half22float2(*(const __half2*)&t3.y);
            acc.x += n0 * a0.x + n1 * b0.x + n2 * c0.x + n3 * d0.x;
            acc.y += n0 * a0.y + n1 * b0.y + n2 * c0.y + n3 * d0.y;
            acc.z += n0 * a1.x + n1 * b1.x + n2 * c1.x + n3 * d1.x;
            acc.w += n0 * a1.y + n1 * b1.y + n2 * c1.y + n3 * d1.y;
        }
        for (; j < end; j++) {
            int2 e0 = g_ep[j];
            float n0 = __int_as_float(e0.y);
            uint2 t0 = h4[(size_t)e0.x * 32 + lane];
            float2 a0 = __half22float2(*(const __half2*)&t0.x);
            float2 a1 = __half22float2(*(const __half2*)&t0.y);
            acc.x += n0 * a0.x;
            acc.y += n0 * a0.y;
            acc.z += n0 * a1.x;
            acc.w += n0 * a1.y;
        }
        ((float4*)g_ax)[(size_t)n * 32 + lane] = acc;
    }
}

// ---------------- final aggregation (C=128, fp16 input, bias, CLEAN) ----------------
__global__ void __launch_bounds__(256) k_aggh(const __half* __restrict__ h,
                                              const float* __restrict__ bias,
                                              float* __restrict__ out) {
    const int gtid = blockIdx.x * blockDim.x + threadIdx.x;
    const int warp = gtid >> 5;
    const int lane = threadIdx.x & 31;
    if (warp >= N_NODES) return;
    const uint2* h4 = (const uint2*)h;
    float di = g_dinv[warp];
    float sw = di * di;

    int beg = g_rp[warp] + g_boff[warp >> 8];
    int end = (warp + 1 < N_NODES) ? (g_rp[warp + 1] + g_boff[(warp + 1) >> 8]) : N_EDGES;

    // re-zero accumulators for next replay
    if (lane == 0) g_dega[warp] = 0.0f;
    else if (lane == 1) g_cnt[warp] = 0;

    float4 acc;
    {
        uint2 hv = h4[(size_t)warp * 32 + lane];
        float2 f0 = __half22float2(*(const __half2*)&hv.x);
        float2 f1 = __half22float2(*(const __half2*)&hv.y);
        float4 bv = ((const float4*)bias)[lane];
        acc = make_float4(bv.x + sw * f0.x, bv.y + sw * f0.y,
                          bv.z + sw * f1.x, bv.w + sw * f1.y);
    }

    int j = beg;
    for (; j + 3 < end; j += 4) {
        int2 e0 = g_ep[j],   e1 = g_ep[j+1], e2 = g_ep[j+2], e3 = g_ep[j+3];
        uint2 t0 = h4[(size_t)e0.x * 32 + lane];
        uint2 t1 = h4[(size_t)e1.x * 32 + lane];
        uint2 t2 = h4[(size_t)e2.x * 32 + lane];
        uint2 t3 = h4[(size_t)e3.x * 32 + lane];
        float n0 = __int_as_float(e0.y), n1 = __int_as_float(e1.y);
        float n2 = __int_as_float(e2.y), n3 = __int_as_float(e3.y);
        float2 a0 = __half22float2(*(const __half2*)&t0.x);
        float2 a1 = __half22float2(*(const __half2*)&t0.y);
        float2 b0 = __half22float2(*(const __half2*)&t1.x);
        float2 b1 = __half22float2(*(const __half2*)&t1.y);
        float2 c0 = __half22float2(*(const __half2*)&t2.x);
        float2 c1 = __half22float2(*(const __half2*)&t2.y);
        float2 d0 = __half22float2(*(const __half2*)&t3.x);
        float2 d1 = __half22float2(*(const __half2*)&t3.y);
        acc.x += n0 * a0.x + n1 * b0.x + n2 * c0.x + n3 * d0.x;
        acc.y += n0 * a0.y + n1 * b0.y + n2 * c0.y + n3 * d0.y;
        acc.z += n0 * a1.x + n1 * b1.x + n2 * c1.x + n3 * d1.x;
        acc.w += n0 * a1.y + n1 * b1.y + n2 * c1.y + n3 * d1.y;
    }
    for (; j < end; j++) {
        int2 e0 = g_ep[j];
        float n0 = __int_as_float(e0.y);
        uint2 t0 = h4[(size_t)e0.x * 32 + lane];
        float2 a0 = __half22float2(*(const __half2*)&t0.x);
        float2 a1 = __half22float2(*(const __half2*)&t0.y);
        acc.x += n0 * a0.x;
        acc.y += n0 * a0.y;
        acc.z += n0 * a1.x;
        acc.w += n0 * a1.y;
    }
    ((float4*)out)[(size_t)warp * 32 + lane] = acc;
}

// ---------------- tf32 tensor-core GEMM ----------------
// MODE 1: A fp32; epilogue relu(acc+bias)*mask*2 -> fp16.  MODE 2: A fp16 -> fp16.
template <int MODE>
__global__ void __launch_bounds__(256) k_gemm_tc(const void* __restrict__ Ap,
                                                 const float* __restrict__ B,
                                                 const float* __restrict__ bias,
                                                 __half* __restrict__ Cout,
                                                 int M, int Nn, int K) {
    __shared__ uint32_t As[128][12];
    __shared__ uint32_t Bs[8][136];
    const int tid  = threadIdx.x;
    const int brow = blockIdx.y * 128;
    const int bcol = blockIdx.x * 128;
    const int warp = tid >> 5, lane = tid & 31;
    const int wm = warp & 3, wn = warp >> 2;
    const int g  = lane >> 2, tg = lane & 3;

    float acc[2][8][4];
#pragma unroll
    for (int mt = 0; mt < 2; mt++)
#pragma unroll
        for (int nt = 0; nt < 8; nt++)
#pragma unroll
            for (int r = 0; r < 4; r++) acc[mt][nt][r] = 0.0f;

    const int arow = tid >> 1;
    const int acol = (tid & 1) * 4;
    const int bk   = tid >> 5;
    const int bcl  = (tid & 31) * 4;
    const int ar_g = brow + arow;
    const bool a_ok = ar_g < M;

    float4 av = make_float4(0.f, 0.f, 0.f, 0.f);
    if (a_ok) {
        if (MODE == 1) {
            av = *(const float4*)&((const float*)Ap)[(size_t)ar_g * K + acol];
        } else {
            uint2 hv = *(const uint2*)&((const __half*)Ap)[(size_t)ar_g * K + acol];
            float2 f0 = __half22float2(*(const __half2*)&hv.x);
            float2 f1 = __half22float2(*(const __half2*)&hv.y);
            av = make_float4(f0.x, f0.y, f1.x, f1.y);
        }
    }
    float4 bv = *(const float4*)&B[(size_t)bk * Nn + bcol + bcl];

    const int n_iter = K >> 3;
    for (int it = 0; it < n_iter; it++) {
        *(uint4*)&As[arow][acol] =
            make_uint4(f2tf32(av.x), f2tf32(av.y), f2tf32(av.z), f2tf32(av.w));
        *(uint4*)&Bs[bk][bcl] =
            make_uint4(f2tf32(bv.x), f2tf32(bv.y), f2tf32(bv.z), f2tf32(bv.w));
        __syncthreads();
        if (it + 1 < n_iter) {
            int k0 = (it + 1) << 3;
            av = make_float4(0.f, 0.f, 0.f, 0.f);
            if (a_ok) {
                if (MODE == 1) {
                    av = *(const float4*)&((const float*)Ap)[(size_t)ar_g * K + k0 + acol];
                } else {
                    uint2 hv = *(const uint2*)&((const __half*)Ap)[(size_t)ar_g * K + k0 + acol];
                    float2 f0 = __half22float2(*(const __half2*)&hv.x);
                    float2 f1 = __half22float2(*(const __half2*)&hv.y);
                    av = make_float4(f0.x, f0.y, f1.x, f1.y);
                }
            }
            bv = *(const float4*)&B[(size_t)(k0 + bk) * Nn + bcol + bcl];
        }
        uint32_t af[2][4];
#pragma unroll
        for (int mt = 0; mt < 2; mt++) {
            int rb = wm * 32 + mt * 16;
            af[mt][0] = As[rb + g][tg];
            af[mt][1] = As[rb + g + 8][tg];
            af[mt][2] = As[rb + g][tg + 4];
            af[mt][3] = As[rb + g + 8][tg + 4];
        }
#pragma unroll
        for (int nt = 0; nt < 8; nt++) {
            int cb = wn * 64 + nt * 8 + g;
            uint32_t b0 = Bs[tg][cb];
            uint32_t b1 = Bs[tg + 4][cb];
#pragma unroll
            for (int mt = 0; mt < 2; mt++) {
                asm volatile(
                    "mma.sync.aligned.m16n8k8.row.col.f32.tf32.tf32.f32 "
                    "{%0,%1,%2,%3}, {%4,%5,%6,%7}, {%8,%9}, {%0,%1,%2,%3};\n"
                    : "+f"(acc[mt][nt][0]), "+f"(acc[mt][nt][1]),
                      "+f"(acc[mt][nt][2]), "+f"(acc[mt][nt][3])
                    : "r"(af[mt][0]), "r"(af[mt][1]), "r"(af[mt][2]), "r"(af[mt][3]),
                      "r"(b0), "r"(b1));
            }
        }
        __syncthreads();
    }

    const uint32_t* maskw = (const uint32_t*)g_mask8;
#pragma unroll
    for (int mt = 0; mt < 2; mt++) {
#pragma unroll
        for (int half = 0; half < 2; half++) {
            int row = brow + wm * 32 + mt * 16 + g + half * 8;
            if (row >= M) continue;
            uint32_t w0 = 0, w1 = 0;
            if (MODE == 1) {
                int wbase = row * 8 + ((bcol + wn * 64) >> 5);
                w0 = maskw[wbase + 0];
                w1 = maskw[wbase + 1];
            }
#pragma unroll
            for (int nt = 0; nt < 8; nt++) {
                int coff = nt * 8 + tg * 2;
                int col  = bcol + wn * 64 + coff;
                float v0 = acc[mt][nt][half * 2 + 0];
                float v1 = acc[mt][nt][half * 2 + 1];
                if (MODE == 1) {
                    v0 = fmaxf(v0 + __ldg(&bias[col]), 0.0f);
                    v1 = fmaxf(v1 + __ldg(&bias[col + 1]), 0.0f);
                    uint32_t w = (coff < 32) ? w0 : w1;
                    int bit = coff & 31;
                    v0 = (w >> bit & 1u)       ? 2.0f * v0 : 0.0f;
                    v1 = (w >> (bit + 1) & 1u) ? 2.0f * v1 : 0.0f;
                }
                __half2 hv = __floats2half2_rn(v0, v1);
                *(__half2*)&Cout[(size_t)row * Nn + col] = hv;
            }
        }
    }
}

// ---------------- launch ----------------
extern "C" void kernel_launch(void* const* d_in, const int* in_sizes, int n_in,
                              void* d_out, int out_size) {
    const float* x = nullptr; const void* ei = nullptr; const float* w = nullptr;
    const float* W1 = nullptr; const float* b1 = nullptr;
    const float* W2 = nullptr; const float* b2 = nullptr;
    for (int i = 0; i < n_in; i++) {
        int sz = in_sizes[i];
        const void* p = d_in[i];
        switch (sz) {
            case 6400000: x  = (const float*)p; break;
            case 1600000: ei = p; break;
            case 800000:  w  = (const float*)p; break;
            case 32768:   if (!W1) W1 = (const float*)p; else W2 = (const float*)p; break;
            case 256:     b1 = (const float*)p; break;
            case 128:     b2 = (const float*)p; break;
            default: break;
        }
    }
    float* out = (float*)d_out;

    float*  ax;  cudaGetSymbolAddress((void**)&ax,  g_ax);
    __half* h1h; cudaGetSymbolAddress((void**)&h1h, g_h1h);
    __half* h2h; cudaGetSymbolAddress((void**)&h2h, g_h2h);

    // cooperative grid size: computed once (uncaptured correctness call)
    static int coop_blocks = 0;
    if (!coop_blocks) {
        int nb = 0, nsm = 0, dev = 0;
        cudaGetDevice(&dev);
        cudaDeviceGetAttribute(&nsm, cudaDevAttrMultiProcessorCount, dev);
        cudaOccupancyMaxActiveBlocksPerMultiprocessor(&nb, k_prep_all, 256, 0);
        if (nb < 1) nb = 1;
        coop_blocks = nb * nsm;
    }

    // 4 launches total
    void* args[] = {(void*)&x, (void*)&ei, (void*)&w};
    cudaLaunchCooperativeKernel((void*)k_prep_all, dim3(coop_blocks), dim3(256),
                                args, 0, (cudaStream_t)0);
    k_gemm_tc<1><<<dim3(C_HID / 128, (N_NODES + 127) / 128), 256>>>(
        ax, W1, b1, h1h, N_NODES, C_HID, 128);
    k_gemm_tc<2><<<dim3(C_OUT / 128, (N_NODES + 127) / 128), 256>>>(
        h1h, W2, nullptr, h2h, N_NODES, C_OUT, C_HID);
    k_aggh<<<(N_NODES * 32 + 255) / 256, 256>>>(h2h, b2, out);
}

// round 16
// speedup vs baseline: 1.0738x; 1.0738x over previous
#include <cuda_runtime.h>
#include <cuda_fp16.h>
#include <cstdint>
#include <cstddef>

#define N_NODES 50000
#define N_PAD   50048                      // padded row count (multiple of 128)
#define N_EDGES 800000
#define C_HID   256
#define C_OUT   128
#define SCAN_B  512
#define NB      ((N_NODES + SCAN_B - 1) / SCAN_B)   // 98
#define N_MASKB (N_NODES * C_HID / 8)      // 1,600,000 bytes of dropout mask
#define MB_CVT  800000                     // cvtprep: mask bytes [0, 800K)

// ---------------- scratch (static device globals; no allocation) ----------------
// g_dega & g_cnt are accumulators: zero at process start (BSS) and re-zeroed by the
// FINAL kernel of every launch (k_aggh CLEAN), so each replay starts clean.
__device__ __align__(16) float    g_dega[N_NODES];     // deg = 1 + g_dega
__device__ __align__(16) float    g_dinv[N_NODES];
__device__ __align__(16) int      g_src [N_EDGES];
__device__ __align__(16) int      g_dst [N_EDGES];
__device__ __align__(16) int      g_cnt [N_NODES];
__device__ __align__(16) int      g_rp  [N_NODES];     // block-local exclusive scan
__device__ __align__(16) int      g_cur [N_NODES];     // running copy of g_rp
__device__ __align__(16) int      g_bsum[NB];
__device__ __align__(16) int      g_boff[NB];          // block offsets (for agg kernels)
__device__ __align__(16) int2     g_ep  [N_EDGES];     // CSR: packed {src, norm-bits}
__device__ __align__(16) uint8_t  g_mask8[N_MASKB];    // JAX dropout keep-bits
__device__ __align__(16) __half   g_xh  [(size_t)N_NODES * C_OUT];   // x in fp16
__device__ __align__(16) __half   g_axh [(size_t)N_PAD * C_OUT];     // A_hat @ x, fp16
__device__ __align__(16) __half   g_h1h [(size_t)N_PAD * C_HID];     // layer-1 act fp16
__device__ __align__(16) __half   g_h2h [(size_t)N_PAD * C_OUT];     // h1 @ W2 fp16

// ---------------- threefry-2x32 (JAX partitionable convention) ----------------
__device__ __forceinline__ uint32_t rotl32(uint32_t x, int d) {
    return (x << d) | (x >> (32 - d));
}
__device__ __forceinline__ void threefry2x32(uint32_t k0, uint32_t k1,
                                             uint32_t& x0, uint32_t& x1) {
    uint32_t ks0 = k0, ks1 = k1, ks2 = k0 ^ k1 ^ 0x1BD11BDAu;
    x0 += ks0; x1 += ks1;
#define TF_GROUP(a,b,c,d) \
    x0 += x1; x1 = rotl32(x1,a); x1 ^= x0; \
    x0 += x1; x1 = rotl32(x1,b); x1 ^= x0; \
    x0 += x1; x1 = rotl32(x1,c); x1 ^= x0; \
    x0 += x1; x1 = rotl32(x1,d); x1 ^= x0;
    TF_GROUP(13,15,26,6)   x0 += ks1; x1 += ks2 + 1u;
    TF_GROUP(17,29,16,24)  x0 += ks2; x1 += ks0 + 2u;
    TF_GROUP(13,15,26,6)   x0 += ks0; x1 += ks1 + 3u;
    TF_GROUP(17,29,16,24)  x0 += ks1; x1 += ks2 + 4u;
    TF_GROUP(13,15,26,6)   x0 += ks2; x1 += ks0 + 5u;
#undef TF_GROUP
}
// keep ⟺ u<0.5 ⟺ top bit of (y0^y1) clear
__device__ __forceinline__ uint32_t drop_keep_bit(uint32_t i) {
    uint32_t x0 = 0u, x1 = i;
    threefry2x32(0u, 42u, x0, x1);
    return ((x0 ^ x1) >> 31) ^ 1u;
}
// compute mask byte b (elements 8b..8b+7) and store
__device__ __forceinline__ void mask_byte(uint32_t b) {
    uint32_t base = b * 8u;
    uint32_t m = 0;
#pragma unroll
    for (int j = 0; j < 8; j++) m |= drop_keep_bit(base + j) << j;
    g_mask8[b] = (uint8_t)m;
}

__device__ __forceinline__ uint32_t f2tf32(float f) {
    uint32_t r;
    asm("cvt.rna.tf32.f32 %0, %1;" : "=r"(r) : "f"(f));
    return r;
}

// ---------------- cvt x->fp16 + dtype detect + edge decode + mask[0,800K) ----------------
__global__ void __launch_bounds__(256) k_cvtprep(const float* __restrict__ x,
                                                 const void* __restrict__ ei_raw,
                                                 const float* __restrict__ w) {
    __shared__ int s_odd, s_big, s_mode;
    const int t = threadIdx.x;
    const int i = blockIdx.x * blockDim.x + t;
    if (t == 0) { s_odd = 0; s_big = 0; }
    __syncthreads();
    {
        const unsigned* eiw = (const unsigned*)ei_raw;
        unsigned v0 = eiw[2 * t];
        unsigned v1 = eiw[2 * t + 1];
        if (v0 >= 0x30000000u || v1 >= 0x30000000u) atomicOr(&s_big, 1);
        if (v1 != 0u) atomicOr(&s_odd, 1);
    }
    __syncthreads();
    if (t == 0) s_mode = s_big ? 2 : (s_odd ? 1 : 0);
    __syncthreads();

    // x -> fp16 (float4 granularity; grid covers 1.6M)
    if (i < N_NODES * (C_OUT / 4)) {
        float4 v = ((const float4*)x)[i];
        __half2 a = __floats2half2_rn(v.x, v.y);
        __half2 b = __floats2half2_rn(v.z, v.w);
        ((uint2*)g_xh)[i] = make_uint2(*(uint32_t*)&a, *(uint32_t*)&b);
    }
    // edge decode + degree/count accumulation (accumulators pre-zeroed)
    if (i < N_EDGES) {
        int s, d;
        int mode = s_mode;
        if (mode == 2) {
            const float* ei = (const float*)ei_raw;
            s = (int)ei[i];
            d = (int)ei[N_EDGES + i];
        } else if (mode == 1) {
            const int* ei = (const int*)ei_raw;
            s = ei[i];
            d = ei[N_EDGES + i];
        } else {
            const long long* ei = (const long long*)ei_raw;
            s = (int)ei[i];
            d = (int)ei[N_EDGES + i];
        }
        s = min(max(s, 0), N_NODES - 1);
        d = min(max(d, 0), N_NODES - 1);
        g_src[i] = s; g_dst[i] = d;
        atomicAdd(&g_dega[d], w[i]);
        atomicAdd(&g_cnt[d], 1);
    }
    // dropout mask bytes [0, 800K): ALU work hidden under atomic/memory latency
    if (i < MB_CVT) mask_byte((uint32_t)i);
}

// ---------------- scan1: block-local exclusive scan of cnt (+dinv, +cur) ----------------
__global__ void __launch_bounds__(SCAN_B) k_scan1() {
    __shared__ int ws[16];
    int b = blockIdx.x, t = threadIdx.x;
    int i = b * SCAN_B + t;
    int lane = t & 31, wid = t >> 5;
    int v = (i < N_NODES) ? g_cnt[i] : 0;
    if (i < N_NODES) g_dinv[i] = rsqrtf(1.0f + g_dega[i]);   // deg = 1 + sum(w)
    int x = v;
#pragma unroll
    for (int o = 1; o < 32; o <<= 1) {
        int y = __shfl_up_sync(~0u, x, o);
        if (lane >= o) x += y;
    }
    if (lane == 31) ws[wid] = x;
    __syncthreads();
    if (wid == 0) {
        int s = (lane < 16) ? ws[lane] : 0;
#pragma unroll
        for (int o = 1; o < 16; o <<= 1) {
            int y = __shfl_up_sync(~0u, s, o);
            if (lane >= o) s += y;
        }
        if (lane < 16) ws[lane] = s;
    }
    __syncthreads();
    int excl = x - v + (wid > 0 ? ws[wid - 1] : 0);
    if (i < N_NODES) {
        g_rp[i]  = excl;      // block-local; final = + boff[b]
        g_cur[i] = excl;
    }
    if (t == 0) g_bsum[b] = ws[15];
}

// ---------------- scatter (+ in-block scan of bsum) + mask[800K,1.6M) ----------------
__global__ void __launch_bounds__(256) k_scatter(const float* __restrict__ w) {
    __shared__ int sb[256];
    __shared__ int sexcl[128];
    const int t = threadIdx.x;
    int v = (t < NB) ? g_bsum[t] : 0;
    sb[t] = v;
    __syncthreads();
#pragma unroll
    for (int o = 1; o < 256; o <<= 1) {
        int y = (t >= o) ? sb[t - o] : 0;
        __syncthreads();
        sb[t] += y;
        __syncthreads();
    }
    if (t < 128) sexcl[t] = sb[t] - v;
    if (blockIdx.x == 0 && t < NB) g_boff[t] = sb[t] - v;
    __syncthreads();

    int e = blockIdx.x * 256 + t;
    if (e >= N_EDGES) return;
    mask_byte((uint32_t)(MB_CVT + e));      // bytes [800K, 1.6M): fills idle issue slots
    int s = g_src[e], d = g_dst[e];
    float nm = g_dinv[s] * w[e] * g_dinv[d];
    int pos = atomicAdd(&g_cur[d], 1) + sexcl[d >> 9];
    if ((unsigned)pos < N_EDGES) {
        g_ep[pos] = make_int2(s, __float_as_int(nm));
    }
}

// CSR row bounds with lazily-applied block offsets
__device__ __forceinline__ int rp_final(int n) {
    return (n >= N_NODES) ? N_EDGES : (g_rp[n] + g_boff[n >> 9]);
}

// ---------------- CSR gather aggregation over fp16 rows (C=128) ----------------
// MODE 0: agg1 — no bias, output fp16 (g_axh).
// MODE 1: agg2 — bias, CLEAN accumulators, output fp32 (d_out).
// One warp per node; edge meta loaded two-at-a-time via aligned LDG.128.
template <int MODE>
__global__ void __launch_bounds__(256) k_aggh(const __half* __restrict__ h,
                                              const float* __restrict__ bias,
                                              void* __restrict__ out) {
    const int gtid = blockIdx.x * blockDim.x + threadIdx.x;
    const int warp = gtid >> 5;
    const int lane = threadIdx.x & 31;
    if (warp >= N_NODES) return;
    const uint2* h4 = (const uint2*)h;
    float di = g_dinv[warp];
    float sw = di * di;

    int beg = rp_final(warp), end = rp_final(warp + 1);

    if (MODE == 1) {   // re-zero accumulators for next replay
        if (lane == 0) g_dega[warp] = 0.0f;
        else if (lane == 1) g_cnt[warp] = 0;
    }

    float4 acc;
    {
        uint2 hv = h4[(size_t)warp * 32 + lane];
        float2 f0 = __half22float2(*(const __half2*)&hv.x);
        float2 f1 = __half22float2(*(const __half2*)&hv.y);
        acc = make_float4(sw * f0.x, sw * f0.y, sw * f1.x, sw * f1.y);
        if (MODE == 1) {
            float4 bv = ((const float4*)bias)[lane];
            acc.x += bv.x; acc.y += bv.y; acc.z += bv.z; acc.w += bv.w;
        }
    }

    int j = beg;
    // align j to even so int4 (two-edge) loads are 16B-aligned
    if ((j & 1) && j < end) {
        int2 e0 = g_ep[j];
        float n0 = __int_as_float(e0.y);
        uint2 t0 = h4[(size_t)e0.x * 32 + lane];
        float2 a0 = __half22float2(*(const __half2*)&t0.x);
        float2 a1 = __half22float2(*(const __half2*)&t0.y);
        acc.x += n0 * a0.x; acc.y += n0 * a0.y;
        acc.z += n0 * a1.x; acc.w += n0 * a1.y;
        j++;
    }
    for (; j + 3 < end; j += 4) {
        int4 p0 = *(const int4*)&g_ep[j];       // edges j, j+1
        int4 p1 = *(const int4*)&g_ep[j + 2];   // edges j+2, j+3
        uint2 t0 = h4[(size_t)p0.x * 32 + lane];
        uint2 t1 = h4[(size_t)p0.z * 32 + lane];
        uint2 t2 = h4[(size_t)p1.x * 32 + lane];
        uint2 t3 = h4[(size_t)p1.z * 32 + lane];
        float n0 = __int_as_float(p0.y), n1 = __int_as_float(p0.w);
        float n2 = __int_as_float(p1.y), n3 = __int_as_float(p1.w);
        float2 a0 = __half22float2(*(const __half2*)&t0.x);
        float2 a1 = __half22float2(*(const __half2*)&t0.y);
        float2 b0 = __half22float2(*(const __half2*)&t1.x);
        float2 b1 = __half22float2(*(const __half2*)&t1.y);
        float2 c0 = __half22float2(*(const __half2*)&t2.x);
        float2 c1 = __half22float2(*(const __half2*)&t2.y);
        float2 d0 = __half22float2(*(const __half2*)&t3.x);
        float2 d1 = __half22float2(*(const __half2*)&t3.y);
        acc.x += n0 * a0.x + n1 * b0.x + n2 * c0.x + n3 * d0.x;
        acc.y += n0 * a0.y + n1 * b0.y + n2 * c0.y + n3 * d0.y;
        acc.z += n0 * a1.x + n1 * b1.x + n2 * c1.x + n3 * d1.x;
        acc.w += n0 * a1.y + n1 * b1.y + n2 * c1.y + n3 * d1.y;
    }
    for (; j < end; j++) {
        int2 e0 = g_ep[j];
        float n0 = __int_as_float(e0.y);
        uint2 t0 = h4[(size_t)e0.x * 32 + lane];
        float2 a0 = __half22float2(*(const __half2*)&t0.x);
        float2 a1 = __half22float2(*(const __half2*)&t0.y);
        acc.x += n0 * a0.x; acc.y += n0 * a0.y;
        acc.z += n0 * a1.x; acc.w += n0 * a1.y;
    }

    if (MODE == 0) {
        __half2 o0 = __floats2half2_rn(acc.x, acc.y);
        __half2 o1 = __floats2half2_rn(acc.z, acc.w);
        ((uint2*)out)[(size_t)warp * 32 + lane] =
            make_uint2(*(uint32_t*)&o0, *(uint32_t*)&o1);
    } else {
        ((float4*)out)[(size_t)warp * 32 + lane] = acc;
    }
}

// ---------------- tf32 tensor-core GEMM: C[M,Nn] = A[M,K] @ B[K,Nn] ----------------
// A is fp16 (converted to tf32 in smem staging), B fp32 -> tf32. Output fp16.
// MODE 1: epilogue relu(acc+bias) * dropout-mask * 2.  MODE 2: plain.
template <int MODE>
__global__ void __launch_bounds__(256) k_gemm_tc(const __half* __restrict__ Ap,
                                                 const float* __restrict__ B,
                                                 const float* __restrict__ bias,
                                                 __half* __restrict__ Cout,
                                                 int M, int Nn, int K) {
    __shared__ uint32_t As[128][12];   // [m][k], stride 12: conflict-free frags
    __shared__ uint32_t Bs[8][136];    // [k][n], stride 136: conflict-free frags
    const int tid  = threadIdx.x;
    const int brow = blockIdx.y * 128;
    const int bcol = blockIdx.x * 128;
    const int warp = tid >> 5, lane = tid & 31;
    const int wm = warp & 3, wn = warp >> 2;
    const int g  = lane >> 2, tg = lane & 3;

    float acc[2][8][4];
#pragma unroll
    for (int mt = 0; mt < 2; mt++)
#pragma unroll
        for (int nt = 0; nt < 8; nt++)
#pragma unroll
            for (int r = 0; r < 4; r++) acc[mt][nt][r] = 0.0f;

    const int arow = tid >> 1;
    const int acol = (tid & 1) * 4;
    const int bk   = tid >> 5;
    const int bcl  = (tid & 31) * 4;
    const int ar_g = brow + arow;
    const bool a_ok = ar_g < M;

    float4 av = make_float4(0.f, 0.f, 0.f, 0.f);
    if (a_ok) {
        uint2 hv = *(const uint2*)&Ap[(size_t)ar_g * K + acol];
        float2 f0 = __half22float2(*(const __half2*)&hv.x);
        float2 f1 = __half22float2(*(const __half2*)&hv.y);
        av = make_float4(f0.x, f0.y, f1.x, f1.y);
    }
    float4 bv = *(const float4*)&B[(size_t)bk * Nn + bcol + bcl];

    const int n_iter = K >> 3;
    for (int it = 0; it < n_iter; it++) {
        *(uint4*)&As[arow][acol] =
            make_uint4(f2tf32(av.x), f2tf32(av.y), f2tf32(av.z), f2tf32(av.w));
        *(uint4*)&Bs[bk][bcl] =
            make_uint4(f2tf32(bv.x), f2tf32(bv.y), f2tf32(bv.z), f2tf32(bv.w));
        __syncthreads();
        if (it + 1 < n_iter) {
            int k0 = (it + 1) << 3;
            av = make_float4(0.f, 0.f, 0.f, 0.f);
            if (a_ok) {
                uint2 hv = *(const uint2*)&Ap[(size_t)ar_g * K + k0 + acol];
                float2 f0 = __half22float2(*(const __half2*)&hv.x);
                float2 f1 = __half22float2(*(const __half2*)&hv.y);
                av = make_float4(f0.x, f0.y, f1.x, f1.y);
            }
            bv = *(const float4*)&B[(size_t)(k0 + bk) * Nn + bcol + bcl];
        }
        uint32_t af[2][4];
#pragma unroll
        for (int mt = 0; mt < 2; mt++) {
            int rb = wm * 32 + mt * 16;
            af[mt][0] = As[rb + g][tg];
            af[mt][1] = As[rb + g + 8][tg];
            af[mt][2] = As[rb + g][tg + 4];
            af[mt][3] = As[rb + g + 8][tg + 4];
        }
#pragma unroll
        for (int nt = 0; nt < 8; nt++) {
            int cb = wn * 64 + nt * 8 + g;
            uint32_t b0 = Bs[tg][cb];
            uint32_t b1 = Bs[tg + 4][cb];
#pragma unroll
            for (int mt = 0; mt < 2; mt++) {
                asm volatile(
                    "mma.sync.aligned.m16n8k8.row.col.f32.tf32.tf32.f32 "
                    "{%0,%1,%2,%3}, {%4,%5,%6,%7}, {%8,%9}, {%0,%1,%2,%3};\n"
                    : "+f"(acc[mt][nt][0]), "+f"(acc[mt][nt][1]),
                      "+f"(acc[mt][nt][2]), "+f"(acc[mt][nt][3])
                    : "r"(af[mt][0]), "r"(af[mt][1]), "r"(af[mt][2]), "r"(af[mt][3]),
                      "r"(b0), "r"(b1));
            }
        }
        __syncthreads();
    }

    const uint32_t* maskw = (const uint32_t*)g_mask8;   // 8 words per row (256 bits)
#pragma unroll
    for (int mt = 0; mt < 2; mt++) {
#pragma unroll
        for (int half = 0; half < 2; half++) {
            int row = brow + wm * 32 + mt * 16 + g + half * 8;
            if (row >= M) continue;
            uint32_t w0 = 0, w1 = 0;
            if (MODE == 1) {
                int wbase = row * 8 + ((bcol + wn * 64) >> 5);
                w0 = maskw[wbase + 0];
                w1 = maskw[wbase + 1];
            }
#pragma unroll
            for (int nt = 0; nt < 8; nt++) {
                int coff = nt * 8 + tg * 2;               // 0..62 within 64-col slice
                int col  = bcol + wn * 64 + coff;
                float v0 = acc[mt][nt][half * 2 + 0];
                float v1 = acc[mt][nt][half * 2 + 1];
                if (MODE == 1) {
                    v0 = fmaxf(v0 + __ldg(&bias[col]), 0.0f);
                    v1 = fmaxf(v1 + __ldg(&bias[col + 1]), 0.0f);
                    uint32_t w = (coff < 32) ? w0 : w1;
                    int bit = coff & 31;
                    v0 = (w >> bit & 1u)       ? 2.0f * v0 : 0.0f;
                    v1 = (w >> (bit + 1) & 1u) ? 2.0f * v1 : 0.0f;
                }
                __half2 hv = __floats2half2_rn(v0, v1);
                *(__half2*)&Cout[(size_t)row * Nn + col] = hv;
            }
        }
    }
}

// ---------------- launch ----------------
extern "C" void kernel_launch(void* const* d_in, const int* in_sizes, int n_in,
                              void* d_out, int out_size) {
    // Identify inputs by element count (robust to metadata ordering)
    const float* x = nullptr; const void* ei = nullptr; const float* w = nullptr;
    const float* W1 = nullptr; const float* b1 = nullptr;
    const float* W2 = nullptr; const float* b2 = nullptr;
    for (int i = 0; i < n_in; i++) {
        int sz = in_sizes[i];
        const void* p = d_in[i];
        switch (sz) {
            case 6400000: x  = (const float*)p; break;
            case 1600000: ei = p; break;
            case 800000:  w  = (const float*)p; break;
            case 32768:   if (!W1) W1 = (const float*)p; else W2 = (const float*)p; break;
            case 256:     b1 = (const float*)p; break;
            case 128:     b2 = (const float*)p; break;
            default: break;
        }
    }
    float* out = (float*)d_out;

    __half* xh;  cudaGetSymbolAddress((void**)&xh,  g_xh);
    __half* axh; cudaGetSymbolAddress((void**)&axh, g_axh);
    __half* h1h; cudaGetSymbolAddress((void**)&h1h, g_h1h);
    __half* h2h; cudaGetSymbolAddress((void**)&h2h, g_h2h);

    const int TB = 256;
    // 7 launches
    k_cvtprep<<<(N_NODES * (C_OUT / 4) + TB - 1) / TB, TB>>>(x, ei, w);
    k_scan1<<<NB, SCAN_B>>>();
    k_scatter<<<(N_EDGES + TB - 1) / TB, TB>>>(w);
    k_aggh<0><<<(N_NODES * 32 + TB - 1) / TB, TB>>>(xh, nullptr, axh);
    k_gemm_tc<1><<<dim3(C_HID / 128, (N_NODES + 127) / 128), 256>>>(
        axh, W1, b1, h1h, N_NODES, C_HID, 128);
    k_gemm_tc<2><<<dim3(C_OUT / 128, (N_NODES + 127) / 128), 256>>>(
        h1h, W2, nullptr, h2h, N_NODES, C_OUT, C_HID);
    k_aggh<1><<<(N_NODES * 32 + TB - 1) / TB, TB>>>(h2h, b2, out);
}

// round 17
// speedup vs baseline: 1.3559x; 1.2627x over previous
#include <cuda_runtime.h>
#include <cuda_fp16.h>
#include <cstdint>
#include <cstddef>

#define N_NODES 50000
#define N_PAD   50048                      // padded row count (multiple of 128)
#define N_EDGES 800000
#define C_HID   256
#define C_OUT   128
#define SCAN_B  512
#define NB      ((N_NODES + SCAN_B - 1) / SCAN_B)   // 98
#define N_MASKB (N_NODES * C_HID / 8)      // 1,600,000 bytes of dropout mask
#define MB_CVT  800000                     // cvtprep: mask bytes [0, 800K)
#define W1P_N   (64 * 256)                 // W1 packed: 64 k2-rows x 256 cols
#define W2P_N   (128 * 128)                // W2 packed: 128 k2-rows x 128 cols

// ---------------- scratch (static device globals; no allocation) ----------------
// g_dega & g_cnt are accumulators: zero at process start (BSS) and re-zeroed by the
// FINAL kernel of every launch (k_aggh<1>), so each replay starts clean.
__device__ __align__(16) float    g_dega[N_NODES];     // deg = 1 + g_dega
__device__ __align__(16) float    g_dinv[N_NODES];
__device__ __align__(16) int      g_src [N_EDGES];
__device__ __align__(16) int      g_dst [N_EDGES];
__device__ __align__(16) int      g_cnt [N_NODES];
__device__ __align__(16) int      g_rp  [N_NODES];     // block-local exclusive scan
__device__ __align__(16) int      g_cur [N_NODES];     // running copy of g_rp
__device__ __align__(16) int      g_bsum[NB];
__device__ __align__(16) int      g_boff[NB];          // block offsets (for agg kernels)
__device__ __align__(16) int2     g_ep  [N_EDGES];     // CSR: packed {src, norm-bits}
__device__ __align__(16) uint8_t  g_mask8[N_MASKB];    // JAX dropout keep-bits
__device__ __align__(16) __half   g_xh  [(size_t)N_NODES * C_OUT];   // x in fp16
__device__ __align__(16) __half   g_axh [(size_t)N_PAD * C_OUT];     // A_hat @ x, fp16
__device__ __align__(16) __half   g_h1h [(size_t)N_PAD * C_HID];     // layer-1 act fp16
__device__ __align__(16) __half   g_h2h [(size_t)N_PAD * C_OUT];     // h1 @ W2 fp16
__device__ __align__(16) uint32_t g_w1p [W1P_N];       // W1 as half2 k-pairs [k2][n]
__device__ __align__(16) uint32_t g_w2p [W2P_N];       // W2 as half2 k-pairs [k2][n]

// ---------------- threefry-2x32 (JAX partitionable convention) ----------------
__device__ __forceinline__ uint32_t rotl32(uint32_t x, int d) {
    return (x << d) | (x >> (32 - d));
}
__device__ __forceinline__ void threefry2x32(uint32_t k0, uint32_t k1,
                                             uint32_t& x0, uint32_t& x1) {
    uint32_t ks0 = k0, ks1 = k1, ks2 = k0 ^ k1 ^ 0x1BD11BDAu;
    x0 += ks0; x1 += ks1;
#define TF_GROUP(a,b,c,d) \
    x0 += x1; x1 = rotl32(x1,a); x1 ^= x0; \
    x0 += x1; x1 = rotl32(x1,b); x1 ^= x0; \
    x0 += x1; x1 = rotl32(x1,c); x1 ^= x0; \
    x0 += x1; x1 = rotl32(x1,d); x1 ^= x0;
    TF_GROUP(13,15,26,6)   x0 += ks1; x1 += ks2 + 1u;
    TF_GROUP(17,29,16,24)  x0 += ks2; x1 += ks0 + 2u;
    TF_GROUP(13,15,26,6)   x0 += ks0; x1 += ks1 + 3u;
    TF_GROUP(17,29,16,24)  x0 += ks1; x1 += ks2 + 4u;
    TF_GROUP(13,15,26,6)   x0 += ks2; x1 += ks0 + 5u;
#undef TF_GROUP
}
// keep ⟺ u<0.5 ⟺ top bit of (y0^y1) clear
__device__ __forceinline__ uint32_t drop_keep_bit(uint32_t i) {
    uint32_t x0 = 0u, x1 = i;
    threefry2x32(0u, 42u, x0, x1);
    return ((x0 ^ x1) >> 31) ^ 1u;
}
// compute mask byte b (elements 8b..8b+7) and store
__device__ __forceinline__ void mask_byte(uint32_t b) {
    uint32_t base = b * 8u;
    uint32_t m = 0;
#pragma unroll
    for (int j = 0; j < 8; j++) m |= drop_keep_bit(base + j) << j;
    g_mask8[b] = (uint8_t)m;
}

// ---------------- cvt x->fp16 + dtype detect + edge decode + W pack + mask ----------------
__global__ void __launch_bounds__(256) k_cvtprep(const float* __restrict__ x,
                                                 const void* __restrict__ ei_raw,
                                                 const float* __restrict__ w,
                                                 const float* __restrict__ W1,
                                                 const float* __restrict__ W2) {
    __shared__ int s_odd, s_big, s_mode;
    const int t = threadIdx.x;
    const int i = blockIdx.x * blockDim.x + t;
    if (t == 0) { s_odd = 0; s_big = 0; }
    __syncthreads();
    {
        const unsigned* eiw = (const unsigned*)ei_raw;
        unsigned v0 = eiw[2 * t];
        unsigned v1 = eiw[2 * t + 1];
        if (v0 >= 0x30000000u || v1 >= 0x30000000u) atomicOr(&s_big, 1);
        if (v1 != 0u) atomicOr(&s_odd, 1);
    }
    __syncthreads();
    if (t == 0) s_mode = s_big ? 2 : (s_odd ? 1 : 0);
    __syncthreads();

    // x -> fp16 (float4 granularity; grid covers 1.6M)
    if (i < N_NODES * (C_OUT / 4)) {
        float4 v = ((const float4*)x)[i];
        __half2 a = __floats2half2_rn(v.x, v.y);
        __half2 b = __floats2half2_rn(v.z, v.w);
        ((uint2*)g_xh)[i] = make_uint2(*(uint32_t*)&a, *(uint32_t*)&b);
    }
    // weight packing to half2 k-pairs (k even in low half)
    if (i < W1P_N) {
        int k2 = i >> 8, n = i & 255;
        __half2 h = __floats2half2_rn(W1[(2 * k2) * C_HID + n],
                                      W1[(2 * k2 + 1) * C_HID + n]);
        g_w1p[i] = *(uint32_t*)&h;
    } else if (i < W1P_N + W2P_N) {
        int j = i - W1P_N;
        int k2 = j >> 7, n = j & 127;
        __half2 h = __floats2half2_rn(W2[(2 * k2) * C_OUT + n],
                                      W2[(2 * k2 + 1) * C_OUT + n]);
        g_w2p[j] = *(uint32_t*)&h;
    }
    // edge decode + degree/count accumulation (accumulators pre-zeroed)
    if (i < N_EDGES) {
        int s, d;
        int mode = s_mode;
        if (mode == 2) {
            const float* ei = (const float*)ei_raw;
            s = (int)ei[i];
            d = (int)ei[N_EDGES + i];
        } else if (mode == 1) {
            const int* ei = (const int*)ei_raw;
            s = ei[i];
            d = ei[N_EDGES + i];
        } else {
            const long long* ei = (const long long*)ei_raw;
            s = (int)ei[i];
            d = (int)ei[N_EDGES + i];
        }
        s = min(max(s, 0), N_NODES - 1);
        d = min(max(d, 0), N_NODES - 1);
        g_src[i] = s; g_dst[i] = d;
        atomicAdd(&g_dega[d], w[i]);
        atomicAdd(&g_cnt[d], 1);
    }
    // dropout mask bytes [0, 800K): ALU work hidden under atomic/memory latency
    if (i < MB_CVT) mask_byte((uint32_t)i);
}

// ---------------- scan1: block-local exclusive scan of cnt (+dinv, +cur) ----------------
__global__ void __launch_bounds__(SCAN_B) k_scan1() {
    __shared__ int ws[16];
    int b = blockIdx.x, t = threadIdx.x;
    int i = b * SCAN_B + t;
    int lane = t & 31, wid = t >> 5;
    int v = (i < N_NODES) ? g_cnt[i] : 0;
    if (i < N_NODES) g_dinv[i] = rsqrtf(1.0f + g_dega[i]);   // deg = 1 + sum(w)
    int x = v;
#pragma unroll
    for (int o = 1; o < 32; o <<= 1) {
        int y = __shfl_up_sync(~0u, x, o);
        if (lane >= o) x += y;
    }
    if (lane == 31) ws[wid] = x;
    __syncthreads();
    if (wid == 0) {
        int s = (lane < 16) ? ws[lane] : 0;
#pragma unroll
        for (int o = 1; o < 16; o <<= 1) {
            int y = __shfl_up_sync(~0u, s, o);
            if (lane >= o) s += y;
        }
        if (lane < 16) ws[lane] = s;
    }
    __syncthreads();
    int excl = x - v + (wid > 0 ? ws[wid - 1] : 0);
    if (i < N_NODES) {
        g_rp[i]  = excl;      // block-local; final = + boff[b]
        g_cur[i] = excl;
    }
    if (t == 0) g_bsum[b] = ws[15];
}

// ---------------- scatter (+ in-block scan of bsum) + mask[800K,1.6M) ----------------
__global__ void __launch_bounds__(256) k_scatter(const float* __restrict__ w) {
    __shared__ int sb[256];
    __shared__ int sexcl[128];
    const int t = threadIdx.x;
    int v = (t < NB) ? g_bsum[t] : 0;
    sb[t] = v;
    __syncthreads();
#pragma unroll
    for (int o = 1; o < 256; o <<= 1) {
        int y = (t >= o) ? sb[t - o] : 0;
        __syncthreads();
        sb[t] += y;
        __syncthreads();
    }
    if (t < 128) sexcl[t] = sb[t] - v;
    if (blockIdx.x == 0 && t < NB) g_boff[t] = sb[t] - v;
    __syncthreads();

    int e = blockIdx.x * 256 + t;
    if (e >= N_EDGES) return;
    mask_byte((uint32_t)(MB_CVT + e));      // bytes [800K, 1.6M): fills idle issue slots
    int s = g_src[e], d = g_dst[e];
    float nm = g_dinv[s] * w[e] * g_dinv[d];
    int pos = atomicAdd(&g_cur[d], 1) + sexcl[d >> 9];
    if ((unsigned)pos < N_EDGES) {
        g_ep[pos] = make_int2(s, __float_as_int(nm));
    }
}

// CSR row bounds with lazily-applied block offsets
__device__ __forceinline__ int rp_final(int n) {
    return (n >= N_NODES) ? N_EDGES : (g_rp[n] + g_boff[n >> 9]);
}

// ---------------- CSR gather aggregation over fp16 rows (C=128) ----------------
// MODE 0: agg1 — no bias, output fp16 (g_axh).
// MODE 1: agg2 — bias, CLEAN accumulators, output fp32 (d_out).
template <int MODE>
__global__ void __launch_bounds__(256) k_aggh(const __half* __restrict__ h,
                                              const float* __restrict__ bias,
                                              void* __restrict__ out) {
    const int gtid = blockIdx.x * blockDim.x + threadIdx.x;
    const int warp = gtid >> 5;
    const int lane = threadIdx.x & 31;
    if (warp >= N_NODES) return;
    const uint2* h4 = (const uint2*)h;
    float di = g_dinv[warp];
    float sw = di * di;

    int beg = rp_final(warp), end = rp_final(warp + 1);

    if (MODE == 1) {   // re-zero accumulators for next replay
        if (lane == 0) g_dega[warp] = 0.0f;
        else if (lane == 1) g_cnt[warp] = 0;
    }

    float4 acc;
    {
        uint2 hv = h4[(size_t)warp * 32 + lane];
        float2 f0 = __half22float2(*(const __half2*)&hv.x);
        float2 f1 = __half22float2(*(const __half2*)&hv.y);
        acc = make_float4(sw * f0.x, sw * f0.y, sw * f1.x, sw * f1.y);
        if (MODE == 1) {
            float4 bv = ((const float4*)bias)[lane];
            acc.x += bv.x; acc.y += bv.y; acc.z += bv.z; acc.w += bv.w;
        }
    }

    int j = beg;
    for (; j + 3 < end; j += 4) {
        int2 e0 = g_ep[j],   e1 = g_ep[j+1], e2 = g_ep[j+2], e3 = g_ep[j+3];
        uint2 t0 = h4[(size_t)e0.x * 32 + lane];
        uint2 t1 = h4[(size_t)e1.x * 32 + lane];
        uint2 t2 = h4[(size_t)e2.x * 32 + lane];
        uint2 t3 = h4[(size_t)e3.x * 32 + lane];
        float n0 = __int_as_float(e0.y), n1 = __int_as_float(e1.y);
        float n2 = __int_as_float(e2.y), n3 = __int_as_float(e3.y);
        float2 a0 = __half22float2(*(const __half2*)&t0.x);
        float2 a1 = __half22float2(*(const __half2*)&t0.y);
        float2 b0 = __half22float2(*(const __half2*)&t1.x);
        float2 b1 = __half22float2(*(const __half2*)&t1.y);
        float2 c0 = __half22float2(*(const __half2*)&t2.x);
        float2 c1 = __half22float2(*(const __half2*)&t2.y);
        float2 d0 = __half22float2(*(const __half2*)&t3.x);
        float2 d1 = __half22float2(*(const __half2*)&t3.y);
        acc.x += n0 * a0.x + n1 * b0.x + n2 * c0.x + n3 * d0.x;
        acc.y += n0 * a0.y + n1 * b0.y + n2 * c0.y + n3 * d0.y;
        acc.z += n0 * a1.x + n1 * b1.x + n2 * c1.x + n3 * d1.x;
        acc.w += n0 * a1.y + n1 * b1.y + n2 * c1.y + n3 * d1.y;
    }
    for (; j < end; j++) {
        int2 e0 = g_ep[j];
        float n0 = __int_as_float(e0.y);
        uint2 t0 = h4[(size_t)e0.x * 32 + lane];
        float2 a0 = __half22float2(*(const __half2*)&t0.x);
        float2 a1 = __half22float2(*(const __half2*)&t0.y);
        acc.x += n0 * a0.x; acc.y += n0 * a0.y;
        acc.z += n0 * a1.x; acc.w += n0 * a1.y;
    }

    if (MODE == 0) {
        __half2 o0 = __floats2half2_rn(acc.x, acc.y);
        __half2 o1 = __floats2half2_rn(acc.z, acc.w);
        ((uint2*)out)[(size_t)warp * 32 + lane] =
            make_uint2(*(uint32_t*)&o0, *(uint32_t*)&o1);
    } else {
        ((float4*)out)[(size_t)warp * 32 + lane] = acc;
    }
}

// ---------------- fp16 tensor-core GEMM: C[M,Nn] = A[M,K] @ B[K,Nn] ----------------
// A fp16 row-major; B pre-packed half2 k-pairs [K/2][Nn]. mma.m16n8k16, fp32 accum.
// BM=128, BN=128, BK=16. 256 threads = 8 warps (4 m x 2 n slices, 32x64 each).
// MODE 1: epilogue relu(acc+bias) * dropout-mask * 2 -> fp16.  MODE 2: plain -> fp16.
template <int MODE>
__global__ void __launch_bounds__(256) k_gemm_fp16(const __half* __restrict__ Ap,
                                                   const uint32_t* __restrict__ Bp,
                                                   const float* __restrict__ bias,
                                                   __half* __restrict__ Cout,
                                                   int M, int Nn, int K) {
    __shared__ uint32_t As[128][12];   // [m][k2], cols 0..7 used; stride 12
    __shared__ uint32_t Bs[8][136];    // [k2][n]; stride 136
    const int tid  = threadIdx.x;
    const int brow = blockIdx.y * 128;
    const int bcol = blockIdx.x * 128;
    const int warp = tid >> 5, lane = tid & 31;
    const int wm = warp & 3, wn = warp >> 2;
    const int g  = lane >> 2, tg = lane & 3;

    float acc[2][8][4];
#pragma unroll
    for (int mt = 0; mt < 2; mt++)
#pragma unroll
        for (int nt = 0; nt < 8; nt++)
#pragma unroll
            for (int r = 0; r < 4; r++) acc[mt][nt][r] = 0.0f;

    const int arow  = tid >> 1;          // 0..127
    const int acol4 = (tid & 1) * 4;     // uint32 col 0 or 4 (8 halves each)
    const int bk2   = tid >> 5;          // 0..7 (k2 row within tile)
    const int bcl   = (tid & 31) * 4;    // 0..124 (uint32 cols)
    const int ar_g  = brow + arow;
    const bool a_ok = ar_g < M;

    uint4 av = make_uint4(0, 0, 0, 0);
    if (a_ok) av = *(const uint4*)&Ap[(size_t)ar_g * K + acol4 * 2];
    uint4 bv = *(const uint4*)&Bp[(size_t)bk2 * Nn + bcol + bcl];

    const int n_iter = K >> 4;
    for (int it = 0; it < n_iter; it++) {
        *(uint4*)&As[arow][acol4] = av;
        *(uint4*)&Bs[bk2][bcl]    = bv;
        __syncthreads();
        if (it + 1 < n_iter) {
            int k0 = (it + 1) << 4;
            av = make_uint4(0, 0, 0, 0);
            if (a_ok) av = *(const uint4*)&Ap[(size_t)ar_g * K + k0 + acol4 * 2];
            bv = *(const uint4*)&Bp[(size_t)((k0 >> 1) + bk2) * Nn + bcol + bcl];
        }
        uint32_t af[2][4];
#pragma unroll
        for (int mt = 0; mt < 2; mt++) {
            int rb = wm * 32 + mt * 16;
            af[mt][0] = As[rb + g][tg];          // row g,   k 2tg..2tg+1
            af[mt][1] = As[rb + g + 8][tg];      // row g+8, k 2tg..2tg+1
            af[mt][2] = As[rb + g][tg + 4];      // row g,   k 2tg+8..9
            af[mt][3] = As[rb + g + 8][tg + 4];  // row g+8, k 2tg+8..9
        }
#pragma unroll
        for (int nt = 0; nt < 8; nt++) {
            int cb = wn * 64 + nt * 8 + g;
            uint32_t b0 = Bs[tg][cb];            // col cb, k 2tg..2tg+1
            uint32_t b1 = Bs[tg + 4][cb];        // col cb, k 2tg+8..9
#pragma unroll
            for (int mt = 0; mt < 2; mt++) {
                asm volatile(
                    "mma.sync.aligned.m16n8k16.row.col.f32.f16.f16.f32 "
                    "{%0,%1,%2,%3}, {%4,%5,%6,%7}, {%8,%9}, {%0,%1,%2,%3};\n"
                    : "+f"(acc[mt][nt][0]), "+f"(acc[mt][nt][1]),
                      "+f"(acc[mt][nt][2]), "+f"(acc[mt][nt][3])
                    : "r"(af[mt][0]), "r"(af[mt][1]), "r"(af[mt][2]), "r"(af[mt][3]),
                      "r"(b0), "r"(b1));
            }
        }
        __syncthreads();
    }

    const uint32_t* maskw = (const uint32_t*)g_mask8;   // 8 words per row (256 bits)
#pragma unroll
    for (int mt = 0; mt < 2; mt++) {
#pragma unroll
        for (int half = 0; half < 2; half++) {
            int row = brow + wm * 32 + mt * 16 + g + half * 8;
            if (row >= M) continue;
            uint32_t w0 = 0, w1 = 0;
            if (MODE == 1) {
                int wbase = row * 8 + ((bcol + wn * 64) >> 5);
                w0 = maskw[wbase + 0];
                w1 = maskw[wbase + 1];
            }
#pragma unroll
            for (int nt = 0; nt < 8; nt++) {
                int coff = nt * 8 + tg * 2;               // 0..62 within 64-col slice
                int col  = bcol + wn * 64 + coff;
                float v0 = acc[mt][nt][half * 2 + 0];
                float v1 = acc[mt][nt][half * 2 + 1];
                if (MODE == 1) {
                    v0 = fmaxf(v0 + __ldg(&bias[col]), 0.0f);
                    v1 = fmaxf(v1 + __ldg(&bias[col + 1]), 0.0f);
                    uint32_t w = (coff < 32) ? w0 : w1;
                    int bit = coff & 31;
                    v0 = (w >> bit & 1u)       ? 2.0f * v0 : 0.0f;
                    v1 = (w >> (bit + 1) & 1u) ? 2.0f * v1 : 0.0f;
                }
                __half2 hv = __floats2half2_rn(v0, v1);
                *(__half2*)&Cout[(size_t)row * Nn + col] = hv;
            }
        }
    }
}

// ---------------- launch ----------------
extern "C" void kernel_launch(void* const* d_in, const int* in_sizes, int n_in,
                              void* d_out, int out_size) {
    // Identify inputs by element count (robust to metadata ordering)
    const float* x = nullptr; const void* ei = nullptr; const float* w = nullptr;
    const float* W1 = nullptr; const float* b1 = nullptr;
    const float* W2 = nullptr; const float* b2 = nullptr;
    for (int i = 0; i < n_in; i++) {
        int sz = in_sizes[i];
        const void* p = d_in[i];
        switch (sz) {
            case 6400000: x  = (const float*)p; break;
            case 1600000: ei = p; break;
            case 800000:  w  = (const float*)p; break;
            case 32768:   if (!W1) W1 = (const float*)p; else W2 = (const float*)p; break;
            case 256:     b1 = (const float*)p; break;
            case 128:     b2 = (const float*)p; break;
            default: break;
        }
    }
    float* out = (float*)d_out;

    __half*   xh;  cudaGetSymbolAddress((void**)&xh,  g_xh);
    __half*   axh; cudaGetSymbolAddress((void**)&axh, g_axh);
    __half*   h1h; cudaGetSymbolAddress((void**)&h1h, g_h1h);
    __half*   h2h; cudaGetSymbolAddress((void**)&h2h, g_h2h);
    uint32_t* w1p; cudaGetSymbolAddress((void**)&w1p, g_w1p);
    uint32_t* w2p; cudaGetSymbolAddress((void**)&w2p, g_w2p);

    const int TB = 256;
    // 7 launches
    k_cvtprep<<<(N_NODES * (C_OUT / 4) + TB - 1) / TB, TB>>>(x, ei, w, W1, W2);
    k_scan1<<<NB, SCAN_B>>>();
    k_scatter<<<(N_EDGES + TB - 1) / TB, TB>>>(w);
    k_aggh<0><<<(N_NODES * 32 + TB - 1) / TB, TB>>>(xh, nullptr, axh);
    k_gemm_fp16<1><<<dim3(C_HID / 128, (N_NODES + 127) / 128), 256>>>(
        axh, w1p, b1, h1h, N_NODES, C_HID, 128);
    k_gemm_fp16<2><<<dim3(C_OUT / 128, (N_NODES + 127) / 128), 256>>>(
        h1h, w2p, nullptr, h2h, N_NODES, C_OUT, C_HID);
    k_aggh<1><<<(N_NODES * 32 + TB - 1) / TB, TB>>>(h2h, b2, out);
}